// round 1
// baseline (speedup 1.0000x reference)
#include <cuda_runtime.h>
#include <math.h>

#define Bsz 8
#define Lseq 2048
#define INF 64
#define OUTF 64
#define Hd 128
#define Nst 64
#define NLAY 4
#define L2 4096
#define ROWS (Bsz*Lseq)

// ---------------- persistent scratch (static device arrays; no allocation) ----------------
__device__ float  g_h [ROWS*Hd];     // current activations (B,L,H)
__device__ float  g_hn[ROWS*Hd];     // layernormed
__device__ float  g_y [ROWS*Hd];     // conv output (pre-gelu)
__device__ float2 g_at[Hd*Lseq];     // at_roots (H, L) complex
__device__ float2 g_Kd[Hd*L2];       // kernel spectrum (H, 4096) complex
__device__ float2 g_tw[L2/2];        // twiddles exp(-2*pi*i*m/4096), m < 2048

__device__ __forceinline__ float2 cmulf(float2 a, float2 b) {
    return make_float2(a.x*b.x - a.y*b.y, a.x*b.y + a.y*b.x);
}

// ---------------- twiddle table ----------------
__global__ void twiddle_kernel() {
    int m = blockIdx.x * blockDim.x + threadIdx.x;
    if (m < L2/2) {
        float s, c;
        sincospif(-(float)m / 2048.0f, &s, &c);
        g_tw[m] = make_float2(c, s);
    }
}

// ---------------- encoder: h = x @ enc_w.T + enc_b ----------------
__global__ void encoder_kernel(const float* __restrict__ x,
                               const float* __restrict__ w,
                               const float* __restrict__ bias) {
    const int R = 16;
    __shared__ float xs[R][INF];
    int row0 = blockIdx.x * R;
    int c = threadIdx.x;  // 128 threads = output channel
    for (int idx = c; idx < R*INF; idx += 128)
        xs[idx / INF][idx % INF] = x[(row0 + idx/INF)*INF + (idx % INF)];
    __syncthreads();
    float acc[R];
    float bv = bias[c];
    #pragma unroll
    for (int r = 0; r < R; r++) acc[r] = bv;
    for (int k = 0; k < INF; k++) {
        float wv = w[c*INF + k];
        #pragma unroll
        for (int r = 0; r < R; r++) acc[r] = fmaf(xs[r][k], wv, acc[r]);
    }
    #pragma unroll
    for (int r = 0; r < R; r++) g_h[(row0+r)*Hd + c] = acc[r];
}

// ---------------- layernorm over H ----------------
__global__ void ln_kernel(const float* __restrict__ nw, const float* __restrict__ nb) {
    int warp = (blockIdx.x * blockDim.x + threadIdx.x) >> 5;
    int lane = threadIdx.x & 31;
    if (warp >= ROWS) return;
    const float* row = g_h + (size_t)warp * Hd;
    float v[4];
    float sum = 0.f;
    #pragma unroll
    for (int i = 0; i < 4; i++) { v[i] = row[lane + 32*i]; sum += v[i]; }
    #pragma unroll
    for (int o = 16; o; o >>= 1) sum += __shfl_xor_sync(0xffffffffu, sum, o);
    float mu = sum * (1.0f/Hd);
    float var = 0.f;
    #pragma unroll
    for (int i = 0; i < 4; i++) { float t = v[i]-mu; var += t*t; }
    #pragma unroll
    for (int o = 16; o; o >>= 1) var += __shfl_xor_sync(0xffffffffu, var, o);
    var *= (1.0f/Hd);
    float rstd = rsqrtf(var + 1e-5f);
    float* outr = g_hn + (size_t)warp * Hd;
    #pragma unroll
    for (int i = 0; i < 4; i++) {
        int c = lane + 32*i;
        outr[c] = (v[i]-mu)*rstd*nw[c] + nb[c];
    }
}

// ---------------- cauchy / woodbury: at_roots (H, L) ----------------
__global__ void cauchy_kernel(const float* __restrict__ lre, const float* __restrict__ lim,
                              const float* __restrict__ pre, const float* __restrict__ pim,
                              const float* __restrict__ bre, const float* __restrict__ bim,
                              const float* __restrict__ cre, const float* __restrict__ cim,
                              const float* __restrict__ lstep) {
    int h = blockIdx.x;
    __shared__ float2 slam[Nst], s00[Nst], s01[Nst], s10[Nst], s11[Nst];
    int tid = threadIdx.x;
    if (tid < Nst) {
        int idx = h*Nst + tid;
        slam[tid] = make_float2(lre[idx], lim[idx]);
        float2 P  = make_float2(pre[idx], pim[idx]);
        float2 Bv = make_float2(bre[idx], bim[idx]);
        float2 Cc = make_float2(cre[idx], -cim[idx]);  // conj(C)
        float2 Pc = make_float2(P.x, -P.y);            // conj(P)
        s00[tid] = cmulf(Cc, Bv);
        s01[tid] = cmulf(Cc, P);
        s10[tid] = cmulf(Pc, Bv);
        s11[tid] = cmulf(Pc, P);
    }
    __syncthreads();
    float ts = 2.0f / __expf(lstep[h]);   // 2/step
    for (int l = tid; l < Lseq; l += blockDim.x) {
        // omega = exp(-2*pi*i*l/L), computed like XLA (f32 angle + sincosf).
        // Do NOT use sincospif here: at l=L/2 exact zero would produce NaN;
        // the f32-rounded angle gives a tiny nonzero imag that cancels analytically.
        float ang = -6.2831853071795864f * ((float)l / (float)Lseq);
        float s, c;
        sincosf(ang, &s, &c);
        float dpx = 1.0f + c, dpy = s;      // 1+omega
        float dmx = 1.0f - c, dmy = -s;     // 1-omega
        float id2 = __fdividef(1.0f, dpx*dpx + dpy*dpy);
        float gx = ts * (dmx*dpx + dmy*dpy) * id2;
        float gy = ts * (dmy*dpx - dmx*dpy) * id2;
        float c2x = 2.0f*dpx*id2, c2y = -2.0f*dpy*id2;  // c = 2/(1+omega)
        float k00x=0,k00y=0,k01x=0,k01y=0,k10x=0,k10y=0,k11x=0,k11y=0;
        #pragma unroll 8
        for (int n = 0; n < Nst; n++) {
            float dx = gx - slam[n].x;
            float dy = gy - slam[n].y;
            float inv = __fdividef(1.0f, dx*dx + dy*dy);
            float rx = dx*inv, ry = -dy*inv;  // 1/(g - lam)
            float2 v;
            v = s00[n]; k00x += v.x*rx - v.y*ry; k00y += v.x*ry + v.y*rx;
            v = s01[n]; k01x += v.x*rx - v.y*ry; k01y += v.x*ry + v.y*rx;
            v = s10[n]; k10x += v.x*rx - v.y*ry; k10y += v.x*ry + v.y*rx;
            v = s11[n]; k11x += v.x*rx - v.y*ry; k11y += v.x*ry + v.y*rx;
        }
        // woodbury: at = c * (k00 - k01 * k10 / (1 + k11))
        float opx = 1.0f + k11x, opy = k11y;
        float oinv = __fdividef(1.0f, opx*opx + opy*opy);
        float wx = k01x*k10x - k01y*k10y;
        float wy = k01x*k10y + k01y*k10x;
        float cx = (wx*opx + wy*opy) * oinv;
        float cy = (wy*opx - wx*opy) * oinv;
        float rx = k00x - cx, ry = k00y - cy;
        g_at[h*Lseq + l] = make_float2(c2x*rx - c2y*ry, c2x*ry + c2y*rx);
    }
}

// ---------------- in-smem Stockham radix-2 FFT ----------------
// Returns pointer to buffer holding the result (a if logn even, b if odd).
__device__ float2* block_fft(float2* a, float2* b, int n, int logn, bool inverse) {
    float2* src = a; float2* dst = b;
    int half = n >> 1;
    for (int t = 0; t < logn; t++) {
        __syncthreads();
        int Ls = 1 << t;
        int shift = 11 - t;  // twiddle table has 2048 entries for 4096-root
        for (int j = threadIdx.x; j < half; j += blockDim.x) {
            int k = j & (Ls - 1);
            int blk = j >> t;
            float2 u = src[j];
            float2 v = src[j + half];
            float2 w = g_tw[k << shift];
            float wy = inverse ? -w.y : w.y;
            float twx = w.x*v.x - wy*v.y;
            float twy = w.x*v.y + wy*v.x;
            int o = (blk << (t+1)) + k;
            dst[o]      = make_float2(u.x + twx, u.y + twy);
            dst[o + Ls] = make_float2(u.x - twx, u.y - twy);
        }
        float2* tmp = src; src = dst; dst = tmp;
    }
    __syncthreads();
    return src;
}

// ---------------- K = ifft(at_roots).real ; Kd = fft(K, 4096) ----------------
__global__ void kfft_kernel() {
    extern __shared__ float2 smemf[];
    float2* A  = smemf;
    float2* Bb = smemf + L2;
    int h = blockIdx.x;
    int tid = threadIdx.x;
    for (int l = tid; l < Lseq; l += blockDim.x) A[l] = g_at[h*Lseq + l];
    float2* r1 = block_fft(A, Bb, Lseq, 11, true);   // inverse 2048 -> ends in Bb
    for (int l = tid; l < L2; l += blockDim.x) {
        float kv = (l < Lseq) ? r1[l].x * (1.0f/Lseq) : 0.0f;
        A[l] = make_float2(kv, 0.0f);
    }
    float2* r2 = block_fft(A, Bb, L2, 12, false);    // forward 4096 -> ends in A
    for (int f = tid; f < L2; f += blockDim.x) g_Kd[h*L2 + f] = r2[f];
}

// ---------------- FFT causal conv: y = irfft(fft(hn) * Kd) + hn*d ----------------
__global__ void conv_kernel(const float* __restrict__ dvec) {
    extern __shared__ float2 smemf[];
    float2* A  = smemf;
    float2* Bb = smemf + L2;
    int bh = blockIdx.x;
    int b = bh / Hd, h = bh % Hd;
    int tid = threadIdx.x;
    const float* u = g_hn + (size_t)b*Lseq*Hd + h;   // stride Hd
    for (int l = tid; l < L2; l += blockDim.x) {
        float uv = (l < Lseq) ? u[(size_t)l*Hd] : 0.0f;
        A[l] = make_float2(uv, 0.0f);
    }
    float2* F = block_fft(A, Bb, L2, 12, false);     // in A
    const float2* kd = g_Kd + h*L2;
    for (int f = tid; f < L2; f += blockDim.x)
        F[f] = cmulf(F[f], kd[f]);
    float2* R = block_fft(A, Bb, L2, 12, true);      // in A
    float dv = dvec[h];
    float* yout = g_y + (size_t)b*Lseq*Hd + h;
    for (int l = tid; l < Lseq; l += blockDim.x)
        yout[(size_t)l*Hd] = R[l].x * (1.0f/L2) + u[(size_t)l*Hd] * dv;
}

// ---------------- gelu + gated MLP + residual ----------------
__global__ void mlp_kernel(const float* __restrict__ w1, const float* __restrict__ b1,
                           const float* __restrict__ w2, const float* __restrict__ b2) {
    const int R = 16;
    __shared__ float zs[R][Hd];
    int row0 = blockIdx.x * R;
    int c = threadIdx.x;   // 128 threads
    for (int idx = c; idx < R*Hd; idx += 128) {
        int r = idx >> 7, k = idx & 127;
        float yv = g_y[(size_t)(row0+r)*Hd + k];
        // tanh gelu (jax approximate=True)
        float t = 0.7978845608028654f * (yv + 0.044715f * yv*yv*yv);
        zs[r][k] = 0.5f * yv * (1.0f + tanhf(t));
    }
    __syncthreads();
    float acc1[R], acc2[R];
    float bv1 = b1[c], bv2 = b2[c];
    #pragma unroll
    for (int r = 0; r < R; r++) { acc1[r] = bv1; acc2[r] = bv2; }
    for (int k = 0; k < Hd; k++) {
        float w1v = w1[c*Hd + k];
        float w2v = w2[c*Hd + k];
        #pragma unroll
        for (int r = 0; r < R; r++) {
            float z = zs[r][k];
            acc1[r] = fmaf(z, w1v, acc1[r]);
            acc2[r] = fmaf(z, w2v, acc2[r]);
        }
    }
    #pragma unroll
    for (int r = 0; r < R; r++) {
        float sig = 1.0f / (1.0f + __expf(-acc2[r]));
        float o = acc1[r] * sig;
        size_t idx = (size_t)(row0+r)*Hd + c;
        g_h[idx] = g_h[idx] + o;   // skip + y
    }
}

// ---------------- decoder ----------------
__global__ void dec_kernel(const float* __restrict__ w, const float* __restrict__ bias,
                           float* __restrict__ out) {
    const int R = 32;
    __shared__ float hs[R][Hd];
    int row0 = blockIdx.x * R;
    for (int idx = threadIdx.x; idx < R*Hd; idx += 128)
        hs[idx >> 7][idx & 127] = g_h[(size_t)(row0 + (idx>>7))*Hd + (idx & 127)];
    __syncthreads();
    int o = threadIdx.x & 63;
    int r0 = (threadIdx.x >> 6) * 16;
    float acc[16];
    float bv = bias[o];
    #pragma unroll
    for (int r = 0; r < 16; r++) acc[r] = bv;
    for (int k = 0; k < Hd; k++) {
        float wv = w[o*Hd + k];
        #pragma unroll
        for (int r = 0; r < 16; r++) acc[r] = fmaf(hs[r0+r][k], wv, acc[r]);
    }
    #pragma unroll
    for (int r = 0; r < 16; r++)
        out[(size_t)(row0 + r0 + r)*OUTF + o] = acc[r];
}

// ---------------- launch ----------------
extern "C" void kernel_launch(void* const* d_in, const int* in_sizes, int n_in,
                              void* d_out, int out_size) {
    const float* x       = (const float*)d_in[0];
    // d_in[1] = convolve (static 1) — FFT conv path
    const float* enc_w   = (const float*)d_in[2];
    const float* enc_b   = (const float*)d_in[3];
    const float* dec_w   = (const float*)d_in[4];
    const float* dec_b   = (const float*)d_in[5];
    const float* lam_re  = (const float*)d_in[6];
    const float* lam_im  = (const float*)d_in[7];
    const float* p_re    = (const float*)d_in[8];
    const float* p_im    = (const float*)d_in[9];
    const float* b_re    = (const float*)d_in[10];
    const float* b_im    = (const float*)d_in[11];
    const float* c_re    = (const float*)d_in[12];
    const float* c_im    = (const float*)d_in[13];
    const float* dvec    = (const float*)d_in[14];
    const float* logstep = (const float*)d_in[15];
    const float* norm_w  = (const float*)d_in[16];
    const float* norm_b  = (const float*)d_in[17];
    const float* w1      = (const float*)d_in[18];
    const float* b1      = (const float*)d_in[19];
    const float* w2      = (const float*)d_in[20];
    const float* b2      = (const float*)d_in[21];
    float* out = (float*)d_out;

    int smem = 2 * L2 * (int)sizeof(float2);  // 64 KB
    cudaFuncSetAttribute(kfft_kernel, cudaFuncAttributeMaxDynamicSharedMemorySize, smem);
    cudaFuncSetAttribute(conv_kernel, cudaFuncAttributeMaxDynamicSharedMemorySize, smem);

    twiddle_kernel<<<(L2/2 + 255)/256, 256>>>();
    encoder_kernel<<<ROWS/16, 128>>>(x, enc_w, enc_b);
    for (int i = 0; i < NLAY; i++) {
        ln_kernel<<<ROWS/8, 256>>>(norm_w + i*Hd, norm_b + i*Hd);
        cauchy_kernel<<<Hd, 256>>>(lam_re + i*Hd*Nst, lam_im + i*Hd*Nst,
                                   p_re  + i*Hd*Nst, p_im  + i*Hd*Nst,
                                   b_re  + i*Hd*Nst, b_im  + i*Hd*Nst,
                                   c_re  + i*Hd*Nst, c_im  + i*Hd*Nst,
                                   logstep + i*Hd);
        kfft_kernel<<<Hd, 256, smem>>>();
        conv_kernel<<<Bsz*Hd, 256, smem>>>(dvec + i*Hd);
        mlp_kernel<<<ROWS/16, 128>>>(w1 + i*Hd*Hd, b1 + i*Hd, w2 + i*Hd*Hd, b2 + i*Hd);
    }
    dec_kernel<<<ROWS/32, 128>>>(dec_w, dec_b, out);
}